// round 14
// baseline (speedup 1.0000x reference)
#include <cuda_runtime.h>
#include <cuda_fp16.h>

#define B      64
#define TAPE   262144
#define OUT    65536
#define FANIN  16

// Scratch (allocation-free rule: __device__ globals)
__device__ __half g_tape_T[(size_t)TAPE * B];  // 32 MB: tape^T in fp16 [TAPE, B]
__device__ int    g_is64;                      // 1 if index arrays are int64

// ---------------------------------------------------------------------------
// K1: single pass over tape [B, TAPE], 128 cols per block, 256 threads:
//   (a) out = tape              (8 independent float4 ldcs -> stcs, MLP=8)
//   (b) g_tape_T = (half)tape^T (16B stores, default policy -> L2-resident)
//   (c) block 0 publishes index dtype (int64 high words all zero)
// Measured ~18us for its mandatory DRAM stream — at floor, frozen.
// ---------------------------------------------------------------------------
__global__ void __launch_bounds__(256)
transpose_copy_probe_kernel(const float* __restrict__ tape,
                            float* __restrict__ out,
                            const int* __restrict__ in_idx_w) {
    __shared__ float s[2][64][65];   // [tile][col][batch]
    const int t  = threadIdx.x;      // 0..255
    const int bk = blockIdx.x;       // 0..2047
    const int t0 = bk * 128;         // tape-col base (2 tiles of 64)

    // Phase A: 8 independent float4 loads, then stores + smem staging
    const int q = t & 15;            // col quad within tile
    const int b = t >> 4;            // 0..15 (batch base)
    float4 v[8];
    size_t off[8];
    #pragma unroll
    for (int u = 0; u < 8; u++) {
        const int tile  = u & 1;
        const int batch = b + 16 * (u >> 1);     // 0..63
        off[u] = (size_t)batch * TAPE + t0 + tile * 64 + 4 * q;
        v[u] = __ldcs((const float4*)(tape + off[u]));
    }
    #pragma unroll
    for (int u = 0; u < 8; u++) {
        __stcs((float4*)(out + off[u]), v[u]);
        const int tile  = u & 1;
        const int batch = b + 16 * (u >> 1);
        s[tile][4 * q + 0][batch] = v[u].x;
        s[tile][4 * q + 1][batch] = v[u].y;
        s[tile][4 * q + 2][batch] = v[u].z;
        s[tile][4 * q + 3][batch] = v[u].w;
    }

    // Dtype probe (block 0): int64 => high words of small indices all zero
    if (bk == 0 && t < 32) {
        const bool ok = (in_idx_w[2 * t + 1] == 0) &&
                        (in_idx_w[2 * (t + 32) + 1] == 0);
        const unsigned m = __ballot_sync(0xffffffffu, ok);
        if (t == 0) g_is64 = (m == 0xffffffffu) ? 1 : 0;
    }
    __syncthreads();

    // Phase B: fp16 convert + write tape_T (4 x 16B stores per thread)
    #pragma unroll
    for (int u2 = 0; u2 < 4; u2++) {
        const int idx  = t + 256 * u2;   // 0..1023
        const int row  = idx >> 3;       // 0..127 (col within block)
        const int g    = idx & 7;        // batch octet
        const int tile = row >> 6;
        const int c    = row & 63;
        __half2 h[4];
        #pragma unroll
        for (int k = 0; k < 4; k++)
            h[k] = __floats2half2_rn(s[tile][c][8 * g + 2 * k],
                                     s[tile][c][8 * g + 2 * k + 1]);
        *(uint4*)(g_tape_T + (size_t)(t0 + row) * B + 8 * g) = *(uint4*)h;
    }
}

// ---------------------------------------------------------------------------
// K2: fused gather + dot + activation + scatter. QUARTER-WARP gather:
// block = 16 warps x 4 outputs = 64 outputs; lanes split 8/8/8/8 across the
// warp's 4 outputs; each lane loads a uint4 (= 4 half2 = 8 batches) of its
// output's 128B tape_T row. One warp-f-iteration consumes 4 full rows in ~7
// warp-instructions (LDS.64 + IADD + LDG.128 + 4 HFMA2). s_iw is [f][output]
// so the 4 distinct per-warp LDS addresses hit distinct banks. fp16 partial
// accumulation in 2 f-groups of 8; combine + bias + activation in fp32.
// Scatter goes through s_oi (real output_indices): coalesced when arange.
// ---------------------------------------------------------------------------
__global__ void __launch_bounds__(512, 3)
gather_scatter_kernel(const float* __restrict__ weights,
                      const float* __restrict__ bias,
                      const void*  __restrict__ input_indices,
                      const void*  __restrict__ output_indices,
                      const void*  __restrict__ act_ids,
                      float* __restrict__ out) {
    __shared__ int2  s_iw[1024];     // [f][64 outputs]: (byte_off, half2 w)
    __shared__ float s_bias[64];
    __shared__ int   s_act[64];
    __shared__ int   s_oi[64];
    __shared__ float sx[64][65];     // [output][batch]

    const int t    = threadIdx.x;    // 0..511
    const int o0   = blockIdx.x * 64;
    const int is64 = g_is64;

    #pragma unroll
    for (int r = 0; r < 2; r++) {
        const int i  = t + 512 * r;  // 0..1023
        const int f  = i >> 6;       // fanin slot
        const int lo = i & 63;       // local output
        const size_t gidx = (size_t)(o0 + lo) * FANIN + f;
        const int idx = is64 ? (int)((const long long*)input_indices)[gidx]
                             : ((const int*)input_indices)[gidx];
        const float w = weights[gidx];
        const __half2 wh = __floats2half2_rn(w, w);
        int whbits;
        *(__half2*)&whbits = wh;
        s_iw[i] = make_int2(idx * (B * 2), whbits);
    }
    if (t < 64) {
        s_bias[t] = bias[o0 + t];
        s_act[t]  = is64 ? (int)((const long long*)act_ids)[o0 + t]
                         : ((const int*)act_ids)[o0 + t];
        s_oi[t]   = is64 ? (int)((const long long*)output_indices)[o0 + t]
                         : ((const int*)output_indices)[o0 + t];
    }
    __syncthreads();

    const int warp = t >> 5;                  // 0..15
    const int lane = t & 31;
    const int lo   = 4 * warp + (lane >> 3);  // this lane's local output
    const int c    = lane & 7;                // batch octet: batches 8c..8c+7
    const char* tTr = (const char*)g_tape_T + c * 16;

    // fp16 partial accumulators: [half2 pair 0..3] x [f-group a/b]
    __half2 pa[4], pb[4];
    #pragma unroll
    for (int k = 0; k < 4; k++) {
        pa[k] = __float2half2_rn(0.f);
        pb[k] = __float2half2_rn(0.f);
    }

    #pragma unroll
    for (int f = 0; f < FANIN; f++) {
        const int2 iw = s_iw[f * 64 + lo];        // bank-clean broadcast LDS.64
        const uint4 raw = *(const uint4*)(tTr + iw.x);
        const __half2 wv = *(const __half2*)&iw.y;
        __half2* acc = (f < 8) ? pa : pb;
        acc[0] = __hfma2(wv, *(const __half2*)&raw.x, acc[0]);
        acc[1] = __hfma2(wv, *(const __half2*)&raw.y, acc[1]);
        acc[2] = __hfma2(wv, *(const __half2*)&raw.z, acc[2]);
        acc[3] = __hfma2(wv, *(const __half2*)&raw.w, acc[3]);
    }

    // Combine partials + bias in fp32; activation; stage to smem
    const float bv = s_bias[lo];
    const int   a  = s_act[lo];
    #pragma unroll
    for (int k = 0; k < 4; k++) {
        const float2 fa = __half22float2(pa[k]);
        const float2 fb = __half22float2(pb[k]);
        float x0 = bv + fa.x + fb.x;
        float x1 = bv + fa.y + fb.y;
        if (a == 0) {
            x0 = fmaxf(x0, 0.f); x1 = fmaxf(x1, 0.f);
        } else if (a == 1) {
            x0 = 1.f / (1.f + __expf(-x0));
            x1 = 1.f / (1.f + __expf(-x1));
        } else {
            x0 = tanhf(x0); x1 = tanhf(x1);
        }
        sx[lo][8 * c + 2 * k]     = x0;
        sx[lo][8 * c + 2 * k + 1] = x1;
    }
    __syncthreads();

    // Scatter: thread t -> output column s_oi[t&63], 8 batches (t>>6 + 8r).
    // 64 consecutive threads -> 256B contiguous per batch row when arange.
    const int j  = t & 63;
    const int b0 = t >> 6;           // 0..7
    const int oi = s_oi[j];
    #pragma unroll
    for (int r = 0; r < 8; r++)
        __stcs(out + (size_t)(b0 + 8 * r) * TAPE + oi, sx[j][b0 + 8 * r]);
}

// ---------------------------------------------------------------------------
extern "C" void kernel_launch(void* const* d_in, const int* in_sizes, int n_in,
                              void* d_out, int out_size) {
    const float* tape           = (const float*)d_in[0];
    const float* weights        = (const float*)d_in[1];
    const float* bias           = (const float*)d_in[2];
    const void*  input_indices  = d_in[3];
    const void*  output_indices = d_in[4];
    const void*  act_ids        = d_in[5];
    float* out = (float*)d_out;

    // K1: read tape once -> copy to out + fp16 transpose to tape_T (+ dtype)
    transpose_copy_probe_kernel<<<TAPE / 128, 256>>>(
        tape, out, (const int*)input_indices);

    // K2: quarter-warp gather + HFMA2 dot + activation + scatter
    gather_scatter_kernel<<<OUT / 64, 512>>>(weights, bias, input_indices,
                                             output_indices, act_ids, out);
}

// round 15
// speedup vs baseline: 1.0007x; 1.0007x over previous
#include <cuda_runtime.h>
#include <cuda_fp16.h>

#define B      64
#define TAPE   262144
#define OUT    65536
#define FANIN  16
#define CH     2                 // fanin per pipeline chunk
#define NCH    (FANIN / CH)      // 8 chunks

// Scratch (allocation-free rule: __device__ globals)
__device__ __half g_tape_T[(size_t)TAPE * B];  // 32 MB: tape^T in fp16 [TAPE, B]
__device__ int    g_is64;                      // 1 if index arrays are int64

// ---------------------------------------------------------------------------
// K1: single pass over tape [B, TAPE], 128 cols per block, 256 threads:
//   (a) out = tape              (8 independent float4 ldcs -> stcs, MLP=8)
//   (b) g_tape_T = (half)tape^T (16B stores, default policy -> L2-resident)
//   (c) block 0 publishes index dtype (int64 high words all zero)
// Measured ~18us for its mandatory DRAM stream — at floor, frozen.
// ---------------------------------------------------------------------------
__global__ void __launch_bounds__(256)
transpose_copy_probe_kernel(const float* __restrict__ tape,
                            float* __restrict__ out,
                            const int* __restrict__ in_idx_w) {
    __shared__ float s[2][64][65];   // [tile][col][batch]
    const int t  = threadIdx.x;      // 0..255
    const int bk = blockIdx.x;       // 0..2047
    const int t0 = bk * 128;         // tape-col base (2 tiles of 64)

    // Phase A: 8 independent float4 loads, then stores + smem staging
    const int q = t & 15;            // col quad within tile
    const int b = t >> 4;            // 0..15 (batch base)
    float4 v[8];
    size_t off[8];
    #pragma unroll
    for (int u = 0; u < 8; u++) {
        const int tile  = u & 1;
        const int batch = b + 16 * (u >> 1);     // 0..63
        off[u] = (size_t)batch * TAPE + t0 + tile * 64 + 4 * q;
        v[u] = __ldcs((const float4*)(tape + off[u]));
    }
    #pragma unroll
    for (int u = 0; u < 8; u++) {
        __stcs((float4*)(out + off[u]), v[u]);
        const int tile  = u & 1;
        const int batch = b + 16 * (u >> 1);
        s[tile][4 * q + 0][batch] = v[u].x;
        s[tile][4 * q + 1][batch] = v[u].y;
        s[tile][4 * q + 2][batch] = v[u].z;
        s[tile][4 * q + 3][batch] = v[u].w;
    }

    // Dtype probe (block 0): int64 => high words of small indices all zero
    if (bk == 0 && t < 32) {
        const bool ok = (in_idx_w[2 * t + 1] == 0) &&
                        (in_idx_w[2 * (t + 32) + 1] == 0);
        const unsigned m = __ballot_sync(0xffffffffu, ok);
        if (t == 0) g_is64 = (m == 0xffffffffu) ? 1 : 0;
    }
    __syncthreads();

    // Phase B: fp16 convert + write tape_T (4 x 16B stores per thread)
    #pragma unroll
    for (int u2 = 0; u2 < 4; u2++) {
        const int idx  = t + 256 * u2;   // 0..1023
        const int row  = idx >> 3;       // 0..127 (col within block)
        const int g    = idx & 7;        // batch octet
        const int tile = row >> 6;
        const int c    = row & 63;
        __half2 h[4];
        #pragma unroll
        for (int k = 0; k < 4; k++)
            h[k] = __floats2half2_rn(s[tile][c][8 * g + 2 * k],
                                     s[tile][c][8 * g + 2 * k + 1]);
        *(uint4*)(g_tape_T + (size_t)(t0 + row) * B + 8 * g) = *(uint4*)h;
    }
}

// ---------------------------------------------------------------------------
// K2: cp.async-pipelined gather + HFMA2 dot + activation + scatter.
// 256 threads = 8 warps x 4 outputs = 32 outputs/block. Quarter-warp layout:
// lane>>3 = output-in-warp, lane&7 = batch octet (16B slice of the 128B row).
// Gather loads run global->smem via cp.async.cg (ZERO data registers, so MLP
// no longer trades against occupancy): 8 chunks of 2 fanin, double-buffered
// gbuf, depth-2 group pipeline, no __syncthreads in the loop (each thread
// consumes exactly the bytes it issued). fp16 2-partial accumulation
// (f-groups 0-7 / 8-15), fp32 combine + bias + activation. Scatter via
// real output_indices through sx (coalesced when arange).
// ---------------------------------------------------------------------------
__global__ void __launch_bounds__(256)
gather_scatter_kernel(const float* __restrict__ weights,
                      const float* __restrict__ bias,
                      const void*  __restrict__ input_indices,
                      const void*  __restrict__ output_indices,
                      const void*  __restrict__ act_ids,
                      float* __restrict__ out) {
    __shared__ int     s_off[FANIN][32];     // gather byte offsets [f][lo]
    __shared__ __half2 s_w[FANIN][32];       // broadcast half2 weights [f][lo]
    __shared__ float   s_bias[32];
    __shared__ int     s_act[32];
    __shared__ int     s_oi[32];
    __shared__ __half  gbuf[2][CH][32][64];  // 16 KB staging (double-buffered)
    __shared__ float   sx[32][66];           // [output][batch]

    const int t    = threadIdx.x;    // 0..255
    const int o0   = blockIdx.x * 32;
    const int is64 = g_is64;

    // Metadata: 512 (f, lo) pairs over 256 threads
    #pragma unroll
    for (int r = 0; r < 2; r++) {
        const int i  = t + 256 * r;
        const int f  = i >> 5;       // 0..15
        const int lo = i & 31;
        const size_t gidx = (size_t)(o0 + lo) * FANIN + f;
        const int idx = is64 ? (int)((const long long*)input_indices)[gidx]
                             : ((const int*)input_indices)[gidx];
        const float w = weights[gidx];
        s_off[f][lo] = idx * (B * 2);
        s_w[f][lo]   = __floats2half2_rn(w, w);
    }
    if (t < 32) {
        s_bias[t] = bias[o0 + t];
        s_act[t]  = is64 ? (int)((const long long*)act_ids)[o0 + t]
                         : ((const int*)act_ids)[o0 + t];
        s_oi[t]   = is64 ? (int)((const long long*)output_indices)[o0 + t]
                         : ((const int*)output_indices)[o0 + t];
    }
    __syncthreads();

    const int warp = t >> 5;                  // 0..7
    const int lane = t & 31;
    const int lo   = 4 * warp + (lane >> 3);  // this lane's local output
    const int c    = lane & 7;                // batch octet: batches 8c..8c+7
    const char* tT = (const char*)g_tape_T + c * 16;

    // Issue one chunk: CH cp.async.cg of 16B each (no data registers used)
    auto issue = [&](int chunk) {
        const int stage = chunk & 1;
        #pragma unroll
        for (int fc = 0; fc < CH; fc++) {
            const int f = chunk * CH + fc;
            const char* src = tT + s_off[f][lo];
            const unsigned dst =
                (unsigned)__cvta_generic_to_shared(&gbuf[stage][fc][lo][c * 8]);
            asm volatile("cp.async.cg.shared.global [%0], [%1], 16;"
                         :: "r"(dst), "l"(src) : "memory");
        }
        asm volatile("cp.async.commit_group;" ::: "memory");
    };

    __half2 pa[4], pb[4];
    #pragma unroll
    for (int k = 0; k < 4; k++) {
        pa[k] = __float2half2_rn(0.f);
        pb[k] = __float2half2_rn(0.f);
    }

    issue(0);
    issue(1);
    #pragma unroll
    for (int chunk = 0; chunk < NCH; chunk++) {
        if (chunk < NCH - 1) {
            asm volatile("cp.async.wait_group 1;" ::: "memory");
        } else {
            asm volatile("cp.async.wait_group 0;" ::: "memory");
        }
        const int stage = chunk & 1;
        #pragma unroll
        for (int fc = 0; fc < CH; fc++) {
            const int f = chunk * CH + fc;
            const uint4 raw = *(const uint4*)&gbuf[stage][fc][lo][c * 8];
            const __half2 wv = s_w[f][lo];
            __half2* acc = (f < 8) ? pa : pb;
            acc[0] = __hfma2(wv, *(const __half2*)&raw.x, acc[0]);
            acc[1] = __hfma2(wv, *(const __half2*)&raw.y, acc[1]);
            acc[2] = __hfma2(wv, *(const __half2*)&raw.z, acc[2]);
            acc[3] = __hfma2(wv, *(const __half2*)&raw.w, acc[3]);
        }
        if (chunk + 2 < NCH) issue(chunk + 2);
    }

    // Combine partials + bias in fp32; activation; stage to sx
    const float bv = s_bias[lo];
    const int   a  = s_act[lo];
    #pragma unroll
    for (int k = 0; k < 4; k++) {
        const float2 fa = __half22float2(pa[k]);
        const float2 fb = __half22float2(pb[k]);
        float x0 = bv + fa.x + fb.x;
        float x1 = bv + fa.y + fb.y;
        if (a == 0) {
            x0 = fmaxf(x0, 0.f); x1 = fmaxf(x1, 0.f);
        } else if (a == 1) {
            x0 = 1.f / (1.f + __expf(-x0));
            x1 = 1.f / (1.f + __expf(-x1));
        } else {
            x0 = tanhf(x0); x1 = tanhf(x1);
        }
        sx[lo][8 * c + 2 * k]     = x0;
        sx[lo][8 * c + 2 * k + 1] = x1;
    }
    __syncthreads();

    // Scatter: thread t -> output column s_oi[t&31], 8 batches (t>>5 + 8r).
    // 32 consecutive threads -> 128B contiguous per batch row when arange.
    const int j  = t & 31;
    const int b0 = t >> 5;           // 0..7
    const int oi = s_oi[j];
    #pragma unroll
    for (int r = 0; r < 8; r++)
        __stcs(out + (size_t)(b0 + 8 * r) * TAPE + oi, sx[j][b0 + 8 * r]);
}

// ---------------------------------------------------------------------------
extern "C" void kernel_launch(void* const* d_in, const int* in_sizes, int n_in,
                              void* d_out, int out_size) {
    const float* tape           = (const float*)d_in[0];
    const float* weights        = (const float*)d_in[1];
    const float* bias           = (const float*)d_in[2];
    const void*  input_indices  = d_in[3];
    const void*  output_indices = d_in[4];
    const void*  act_ids        = d_in[5];
    float* out = (float*)d_out;

    // K1: read tape once -> copy to out + fp16 transpose to tape_T (+ dtype)
    transpose_copy_probe_kernel<<<TAPE / 128, 256>>>(
        tape, out, (const int*)input_indices);

    // K2: cp.async-pipelined gather + HFMA2 dot + activation + scatter
    gather_scatter_kernel<<<OUT / 32, 256>>>(weights, bias, input_indices,
                                             output_indices, act_ids, out);
}